// round 15
// baseline (speedup 1.0000x reference)
#include <cuda_runtime.h>
#include <cuda_fp16.h>
#include <cstdint>
#include <cstddef>

#define N_NODES 8192
#define FEAT    256
#define BM      32           // output rows per CTA (main kernel) — row-split
#define BK      32           // k-tile (nodes)
#define NTILES  (N_NODES / BK)   // 256
#define THREADS 256

// Scratch (no runtime allocation allowed)
__device__ __half d_Hh[N_NODES * FEAT];  // h in fp16 (MMA B operand), row-major
__device__ __half d_Wh[FEAT * FEAT];     // W in fp16
__device__ float  d_U[2][FEAT];          // u1 = W@a1, u2 = W@a2
__device__ float4 d_G1[N_NODES];         // (s1, exp(s1), exp(0.2 s1), 0)
__device__ float4 d_G2[N_NODES];         // (s2, exp(s2), exp(0.2 s2), 0)

// ---------------------------------------------------------------------------
// helpers
// ---------------------------------------------------------------------------
__device__ __forceinline__ uint32_t smem_u32(const void* p) {
    uint32_t a;
    asm("{ .reg .u64 t; cvta.to.shared.u64 t, %1; cvt.u32.u64 %0, t; }" : "=r"(a) : "l"(p));
    return a;
}
__device__ __forceinline__ void cp16(void* dst, const void* src) {
    unsigned d = (unsigned)__cvta_generic_to_shared(dst);
    asm volatile("cp.async.cg.shared.global [%0], [%1], 16;" :: "r"(d), "l"(src));
}
__device__ __forceinline__ void cp_commit() {
    asm volatile("cp.async.commit_group;" ::: "memory");
}
template <int N>
__device__ __forceinline__ void cp_wait() {
    asm volatile("cp.async.wait_group %0;" :: "n"(N) : "memory");
}
#define LDSM4(R, addr)                                                          \
    asm volatile("ldmatrix.sync.aligned.m8n8.x4.shared.b16 {%0,%1,%2,%3}, [%4];" \
                 : "=r"((R)[0]), "=r"((R)[1]), "=r"((R)[2]), "=r"((R)[3])       \
                 : "r"(addr))
#define LDSM4T(R, addr)                                                               \
    asm volatile("ldmatrix.sync.aligned.m8n8.x4.trans.shared.b16 {%0,%1,%2,%3}, [%4];" \
                 : "=r"((R)[0]), "=r"((R)[1]), "=r"((R)[2]), "=r"((R)[3])             \
                 : "r"(addr))
#define MMA16816(D, A, B0, B1)                                                  \
    asm volatile("mma.sync.aligned.m16n8k16.row.col.f32.f16.f16.f32 "           \
                 "{%0,%1,%2,%3}, {%4,%5,%6,%7}, {%8,%9}, {%0,%1,%2,%3};"        \
                 : "+f"((D)[0]), "+f"((D)[1]), "+f"((D)[2]), "+f"((D)[3])       \
                 : "r"((A)[0]), "r"((A)[1]), "r"((A)[2]), "r"((A)[3]),          \
                   "r"(B0), "r"(B1))
__device__ __forceinline__ uint32_t h2pack(float a, float b) {
    __half2 h = __floats2half2_rn(a, b);
    return *(uint32_t*)&h;
}

// ---------------------------------------------------------------------------
// Kernel 0: prep — u1 = W@a1, u2 = W@a2 (fp32), and cast W -> fp16.
// (verbatim from passing R13)
// ---------------------------------------------------------------------------
__global__ __launch_bounds__(256) void prep_kernel(const float* __restrict__ W,
                                                   const float* __restrict__ A) {
    __shared__ float a1s[FEAT], a2s[FEAT];
    const int t = threadIdx.x;
    a1s[t] = A[t];
    a2s[t] = A[FEAT + t];
    __syncthreads();
    const int lane = t & 31, wid = t >> 5;
    const int r = blockIdx.x * 8 + wid;
    const float* wr = W + (size_t)r * FEAT;
    float s1 = 0.f, s2 = 0.f;
#pragma unroll
    for (int q = 0; q < 2; q++) {
        int f = lane * 8 + q * 4;
        float4 w4 = *(const float4*)(wr + f);
        uint2 hp;
        hp.x = h2pack(w4.x, w4.y);
        hp.y = h2pack(w4.z, w4.w);
        *(uint2*)(d_Wh + (size_t)r * FEAT + f) = hp;
        s1 += w4.x * a1s[f] + w4.y * a1s[f + 1] + w4.z * a1s[f + 2] + w4.w * a1s[f + 3];
        s2 += w4.x * a2s[f] + w4.y * a2s[f + 1] + w4.z * a2s[f + 2] + w4.w * a2s[f + 3];
    }
#pragma unroll
    for (int o = 16; o > 0; o >>= 1) {
        s1 += __shfl_xor_sync(0xffffffffu, s1, o);
        s2 += __shfl_xor_sync(0xffffffffu, s2, o);
    }
    if (lane == 0) {
        d_U[0][r] = s1;
        d_U[1][r] = s2;
    }
}

// ---------------------------------------------------------------------------
// Kernel 1: spack — s1 = X.u1, s2 = X.u2 (fp32 exact) + separable exp factors.
// (verbatim from passing R13)
// ---------------------------------------------------------------------------
__global__ __launch_bounds__(256) void spack_kernel(const float* __restrict__ X) {
    const int lane = threadIdx.x & 31;
    const int wid  = threadIdx.x >> 5;
    const int row  = blockIdx.x * 8 + wid;
    const float* xr = X + (size_t)row * FEAT;
    float s1 = 0.f, s2 = 0.f;
#pragma unroll
    for (int q = 0; q < 2; q++) {
        int f = lane * 8 + q * 4;
        float4 xv = *(const float4*)(xr + f);
        float4 u1 = *(const float4*)(&d_U[0][f]);
        float4 u2 = *(const float4*)(&d_U[1][f]);
        s1 += xv.x * u1.x + xv.y * u1.y + xv.z * u1.z + xv.w * u1.w;
        s2 += xv.x * u2.x + xv.y * u2.y + xv.z * u2.z + xv.w * u2.w;
    }
#pragma unroll
    for (int o = 16; o > 0; o >>= 1) {
        s1 += __shfl_xor_sync(0xffffffffu, s1, o);
        s2 += __shfl_xor_sync(0xffffffffu, s2, o);
    }
    if (lane == 0) {
        d_G1[row] = make_float4(s1, expf(s1), expf(0.2f * s1), 0.f);
        d_G2[row] = make_float4(s2, expf(s2), expf(0.2f * s2), 0.f);
    }
}

// ---------------------------------------------------------------------------
// Kernel 2: d_Hh = fp16(X @ W) via HMMA (verbatim from passing R13).
// ---------------------------------------------------------------------------
#define GH_SMEM (FEAT * 512)   // 131072

__global__ __launch_bounds__(256, 1) void gemm_h_mma(const float* __restrict__ X) {
    extern __shared__ char sm2[];
    const uint32_t smb = smem_u32(sm2);
    const int t    = threadIdx.x;
    const int wid  = t >> 5, lane = t & 31;
    const int i0   = blockIdx.x * 64;
    const int wM   = wid & 1;
    const int wF   = wid >> 1;

#pragma unroll
    for (int m = 0; m < 32; m++) {
        int e = t + 256 * m;
        int k = e >> 5, c = e & 31;
        cp16(sm2 + k * 512 + ((c ^ (k & 7)) << 4), d_Wh + (size_t)k * FEAT + c * 8);
    }
    cp_commit();
    cp_wait<0>();
    __syncthreads();

    float acc[2][8][4];
#pragma unroll
    for (int a = 0; a < 2; a++)
#pragma unroll
        for (int b = 0; b < 8; b++)
#pragma unroll
            for (int c = 0; c < 4; c++) acc[a][b][c] = 0.f;

    const int g  = lane >> 2;
    const int tg = lane & 3;
    const int bj_lane = lane & 15;
    const int bf_off  = (lane >> 4) * 8;

#pragma unroll 2
    for (int ks = 0; ks < 16; ks++) {
        const int k0 = ks * 16;
        uint32_t afr[2][4];
#pragma unroll
        for (int mf = 0; mf < 2; mf++) {
            const float* xb = X + (size_t)(i0 + wM * 32 + mf * 16 + g) * FEAT + k0 + tg * 2;
            float2 v00 = *(const float2*)(xb);
            float2 v10 = *(const float2*)(xb + 8 * FEAT);
            float2 v01 = *(const float2*)(xb + 8);
            float2 v11 = *(const float2*)(xb + 8 * FEAT + 8);
            afr[mf][0] = h2pack(v00.x, v00.y);
            afr[mf][1] = h2pack(v10.x, v10.y);
            afr[mf][2] = h2pack(v01.x, v01.y);
            afr[mf][3] = h2pack(v11.x, v11.y);
        }
        const int j = k0 + bj_lane;
        const uint32_t brow = smb + j * 512;
        const uint32_t jx   = (uint32_t)(j & 7) << 4;
        uint32_t bfr[4][4];
#pragma unroll
        for (int nf = 0; nf < 4; nf++) {
            int f = wF * 64 + nf * 16 + bf_off;
            uint32_t boff = ((uint32_t)(f >> 3) << 4) ^ jx;
            LDSM4T(bfr[nf], brow + boff);
        }
#pragma unroll
        for (int mf = 0; mf < 2; mf++)
#pragma unroll
            for (int n8 = 0; n8 < 8; n8++)
                MMA16816(acc[mf][n8], afr[mf],
                         bfr[n8 >> 1][(n8 & 1) * 2],
                         bfr[n8 >> 1][(n8 & 1) * 2 + 1]);
    }

#pragma unroll
    for (int mf = 0; mf < 2; mf++) {
        const int ra = i0 + wM * 32 + mf * 16 + g;
#pragma unroll
        for (int n8 = 0; n8 < 8; n8++) {
            const int col = wF * 64 + n8 * 8 + tg * 2;
            *(uint32_t*)(d_Hh + (size_t)ra * FEAT + col) =
                h2pack(acc[mf][n8][0], acc[mf][n8][1]);
            *(uint32_t*)(d_Hh + (size_t)(ra + 8) * FEAT + col) =
                h2pack(acc[mf][n8][2], acc[mf][n8][3]);
        }
    }
}

// ---------------------------------------------------------------------------
// Kernel 3: flash-style fused masked-softmax @ h, fp16 HMMA.
// ROW-SPLIT: BM=32 (grid 256 CTAs, 2 CTAs/SM). Warp tile 16x64.
// RACE FIX vs R14: __syncthreads() AFTER cp_wait and BEFORE consumption —
// cp.async wait_group is per-thread; cross-thread smem visibility needs the
// barrier (canonical wait -> barrier -> consume pattern).
// SMEM layout (dynamic):
//   Hs   : 2 x 16384  (H tile 32(j) x 256(f) fp16, 16B-chunk XOR swizzle) @ 0
//   adjs : 4 x 4096   (adj tile 32 x 32 i32, linear)                     @ 32768
//   Ps   : 2 x 2560   (P tile 32 x 32 fp16, row pitch 80B)               @ 49152
//   g2s  : 4 x 512    (32 float4)                                        @ 54272
//   zsh  : 32 floats                                                     @ 56320
#define HS_OFF   0
#define HS_SZ    16384
#define ADJ_OFF  32768
#define ADJ_SZ   4096
#define PS_OFF   49152
#define PS_SZ    2560
#define G2_OFF   54272
#define ZSH_OFF  56320
#define SMEMM_BYTES 56448
#define PPITCH_B 80     // P row pitch in bytes (40 halves)

__global__ __launch_bounds__(THREADS, 2) void gat_mma_kernel(const int* __restrict__ ADJ,
                                                             float* __restrict__ OUT) {
    extern __shared__ char sm[];
    const uint32_t smb = smem_u32(sm);
    const int t    = threadIdx.x;
    const int wid  = t >> 5, lane = t & 31;
    const int i0   = blockIdx.x * BM;
    const int g    = t & 7;       // P-gen: k-quad (cols 4g..4g+3)
    const int r0   = t >> 3;      // P-gen: my row (0..31)
    const int wM   = wid & 1;     // warp M tile: rows wM*16 .. +15
    const int wF   = wid >> 1;    // warp F tile: cols wF*64 .. +63

    const float4 g1v = d_G1[i0 + r0];
    float zac = 0.f;

    float acc[8][4];              // [n8frag][reg] — 16x64 warp tile
#pragma unroll
    for (int b = 0; b < 8; b++)
#pragma unroll
        for (int c = 0; c < 4; c++) acc[b][c] = 0.f;

    // ---- async loaders ----
    auto load_adj = [&](int s, int ab) {
        const int j0 = s * BK;
        char* adst = sm + ADJ_OFF + ab * ADJ_SZ;
        {
            int r = t >> 3, c = t & 7;   // 32 rows x 8 chunks = 256 slots
            cp16(adst + r * 128 + c * 16, ADJ + (size_t)(i0 + r) * N_NODES + j0 + c * 4);
        }
        if (t < 32) cp16(sm + G2_OFF + ab * 512 + t * 16, d_G2 + j0 + t);
    };
    auto load_h = [&](int s, int hb) {
        const int j0 = s * BK;
        char* hdst = sm + HS_OFF + hb * HS_SZ;
#pragma unroll
        for (int m = 0; m < 4; m++) {
            int e = t + 256 * m;
            int j = e >> 5, c = e & 31;
            cp16(hdst + j * 512 + ((c ^ (j & 7)) << 4),
                 d_Hh + (size_t)(j0 + j) * FEAT + c * 8);
        }
    };

    // ---- P-tile generation for tile sn: w = adj ? exp(lrelu(s1+s2)) : 0 ----
    auto do_genp = [&](int sn) {
        const int ab = sn & 3, pb = sn & 1;
        const float4* g2b = (const float4*)(sm + G2_OFF + ab * 512) + g * 4;
        float4 G[4];
#pragma unroll
        for (int j = 0; j < 4; j++) G[j] = g2b[j];
        const int4* abase = (const int4*)(sm + ADJ_OFF + ab * ADJ_SZ);
        char* pbase = sm + PS_OFF + pb * PS_SZ;
        int4 av = abase[r0 * 8 + g];
        int msk[4] = {av.x, av.y, av.z, av.w};
        __half hw[4];
#pragma unroll
        for (int j = 0; j < 4; j++) {
            float x = g1v.x + G[j].x;
            float e = (x >= 0.f ? g1v.y : g1v.z) *
                      (x >= 0.f ? G[j].y : G[j].z);
            e = (msk[j] != 0) ? e : 0.f;
            hw[j] = __float2half_rn(e);
            zac += __half2float(hw[j]);   // Z from the SAME rounded w
        }
        __half2 p01 = __halves2half2(hw[0], hw[1]);
        __half2 p23 = __halves2half2(hw[2], hw[3]);
        uint2 pk;
        pk.x = *(uint32_t*)&p01;
        pk.y = *(uint32_t*)&p23;
        *(uint2*)(pbase + r0 * PPITCH_B + g * 8) = pk;
    };

    // precomputed ldmatrix address pieces
    const uint32_t a_base = smb + PS_OFF +
                            (uint32_t)(wM * 16 + (lane & 15)) * PPITCH_B +
                            (uint32_t)((lane >> 4) * 8) * 2;
    const int bj_lane = lane & 15;           // row within k-half
    const int bf_off  = (lane >> 4) * 8;     // col offset within n16

    // ---- HMMA for tile s: acc += P[32x32] @ H[32x256] (warp tile 16x64) ----
    auto do_mma = [&](int s) {
        const int cur = s & 1;
        const uint32_t hbase = smb + HS_OFF + cur * HS_SZ;
        const uint32_t acur  = a_base + (uint32_t)cur * PS_SZ;
#pragma unroll
        for (int kh = 0; kh < 2; kh++) {
            uint32_t afr[4];
            LDSM4(afr, acur + kh * 32);            // rows wM*16..+15
            const int j   = kh * 16 + bj_lane;
            const uint32_t brow = hbase + j * 512;
            const uint32_t jx   = (uint32_t)(j & 7) << 4;
            uint32_t bfr[4][4];
#pragma unroll
            for (int nf = 0; nf < 4; nf++) {
                int f = wF * 64 + nf * 16 + bf_off;
                uint32_t boff = ((uint32_t)(f >> 3) << 4) ^ jx;
                LDSM4T(bfr[nf], brow + boff);
            }
#pragma unroll
            for (int n8 = 0; n8 < 8; n8++)
                MMA16816(acc[n8], afr,
                         bfr[n8 >> 1][(n8 & 1) * 2],
                         bfr[n8 >> 1][(n8 & 1) * 2 + 1]);
        }
    };

    // ---- prologue: adj[0] | adj[1]+H[0] in flight; gen P[0] ----
    load_adj(0, 0);
    cp_commit();
    load_adj(1, 1);
    load_h(0, 0);
    cp_commit();
    cp_wait<1>();          // adj[0], g2[0] resident (own groups)
    __syncthreads();       // publish across threads
    do_genp(0);
    __syncthreads();

    // ---- main loop: genP(s+1) overlapped with MMA(s) ----
    for (int s = 0; s < NTILES; ++s) {
        if (s + 1 < NTILES) {
            load_h(s + 1, (s + 1) & 1);
            if (s + 2 < NTILES) load_adj(s + 2, (s + 2) & 3);
            cp_commit();
            cp_wait<1>();  // own group s-1 complete
        } else {
            cp_wait<0>();
        }
        __syncthreads();   // RACE FIX: make ALL threads' cp.async data visible
        // phase-staggered: each SMSP gets one ALU-first and one MMA-first warp
        if ((wid & 4) == 0) {
            if (s + 1 < NTILES) do_genp(s + 1);
            do_mma(s);
        } else {
            do_mma(s);
            if (s + 1 < NTILES) do_genp(s + 1);
        }
        __syncthreads();   // publish Ps[(s+1)&1]; retire reads of Hs[s&1]/Ps[s&1]
    }

    // ---- Z reduction: threads sharing a row differ only in g (low 3 bits) ----
#pragma unroll
    for (int o = 1; o < 8; o <<= 1)
        zac += __shfl_xor_sync(0xffffffffu, zac, o);
    float* zsh = (float*)(sm + ZSH_OFF);
    if (g == 0) zsh[r0] = zac;
    __syncthreads();

    // ---- epilogue: divide by Z, elu, store ----
    {
        const int ra = wM * 16 + (lane >> 2);  // local row a
        const float rza = 1.0f / zsh[ra];
        const float rzb = 1.0f / zsh[ra + 8];
        float* orow_a = OUT + (size_t)(i0 + ra) * FEAT;
        float* orow_b = OUT + (size_t)(i0 + ra + 8) * FEAT;
#pragma unroll
        for (int n8 = 0; n8 < 8; n8++) {
            const int col = wF * 64 + n8 * 8 + (lane & 3) * 2;
            float v0 = acc[n8][0] * rza, v1 = acc[n8][1] * rza;
            float v2 = acc[n8][2] * rzb, v3 = acc[n8][3] * rzb;
            v0 = (v0 > 0.f) ? v0 : expm1f(v0);
            v1 = (v1 > 0.f) ? v1 : expm1f(v1);
            v2 = (v2 > 0.f) ? v2 : expm1f(v2);
            v3 = (v3 > 0.f) ? v3 : expm1f(v3);
            *(float2*)(orow_a + col) = make_float2(v0, v1);
            *(float2*)(orow_b + col) = make_float2(v2, v3);
        }
    }
}

// ---------------------------------------------------------------------------
extern "C" void kernel_launch(void* const* d_in, const int* in_sizes, int n_in,
                              void* d_out, int out_size) {
    (void)in_sizes; (void)n_in; (void)out_size;
    const float* X   = (const float*)d_in[0];   // input [8192,256] f32
    const int*   ADJ = (const int*)d_in[1];     // adj   [8192,8192] i32
    const float* W   = (const float*)d_in[2];   // W     [256,256] f32
    const float* A   = (const float*)d_in[3];   // a     [512,1]  f32
    float* OUT = (float*)d_out;                 // [8192,256] f32

    prep_kernel<<<FEAT / 8, 256>>>(W, A);
    spack_kernel<<<N_NODES / 8, 256>>>(X);
    cudaFuncSetAttribute(gemm_h_mma,
                         cudaFuncAttributeMaxDynamicSharedMemorySize, GH_SMEM);
    gemm_h_mma<<<N_NODES / 64, 256, GH_SMEM>>>(X);
    cudaFuncSetAttribute(gat_mma_kernel,
                         cudaFuncAttributeMaxDynamicSharedMemorySize, SMEMM_BYTES);
    gat_mma_kernel<<<N_NODES / BM, THREADS, SMEMM_BYTES>>>(ADJ, OUT);
}

// round 16
// speedup vs baseline: 1.3352x; 1.3352x over previous
#include <cuda_runtime.h>
#include <cuda_fp16.h>
#include <cstdint>
#include <cstddef>

#define N_NODES 8192
#define FEAT    256
#define BM      64           // output rows per CTA (main kernel)
#define BK      32           // k-tile (nodes)
#define NTILES  (N_NODES / BK)   // 256
#define THREADS 256

// Scratch (no runtime allocation allowed)
__device__ __half d_Hh[N_NODES * FEAT];  // h in fp16 (MMA B operand), row-major
__device__ __half d_Wh[FEAT * FEAT];     // W in fp16
__device__ float  d_U[2][FEAT];          // u1 = W@a1, u2 = W@a2
__device__ float4 d_G1[N_NODES];         // (s1, exp(s1), exp(0.2 s1), 0)
__device__ float4 d_G2[N_NODES];         // (s2, exp(s2), exp(0.2 s2), 0)

// ---------------------------------------------------------------------------
// helpers
// ---------------------------------------------------------------------------
__device__ __forceinline__ uint32_t smem_u32(const void* p) {
    uint32_t a;
    asm("{ .reg .u64 t; cvta.to.shared.u64 t, %1; cvt.u32.u64 %0, t; }" : "=r"(a) : "l"(p));
    return a;
}
__device__ __forceinline__ void cp16(void* dst, const void* src) {
    unsigned d = (unsigned)__cvta_generic_to_shared(dst);
    asm volatile("cp.async.cg.shared.global [%0], [%1], 16;" :: "r"(d), "l"(src));
}
__device__ __forceinline__ void cp_commit() {
    asm volatile("cp.async.commit_group;" ::: "memory");
}
template <int N>
__device__ __forceinline__ void cp_wait() {
    asm volatile("cp.async.wait_group %0;" :: "n"(N) : "memory");
}
#define LDSM4(R, addr)                                                          \
    asm volatile("ldmatrix.sync.aligned.m8n8.x4.shared.b16 {%0,%1,%2,%3}, [%4];" \
                 : "=r"((R)[0]), "=r"((R)[1]), "=r"((R)[2]), "=r"((R)[3])       \
                 : "r"(addr))
#define LDSM4T(R, addr)                                                               \
    asm volatile("ldmatrix.sync.aligned.m8n8.x4.trans.shared.b16 {%0,%1,%2,%3}, [%4];" \
                 : "=r"((R)[0]), "=r"((R)[1]), "=r"((R)[2]), "=r"((R)[3])             \
                 : "r"(addr))
#define MMA16816(D, A, B0, B1)                                                  \
    asm volatile("mma.sync.aligned.m16n8k16.row.col.f32.f16.f16.f32 "           \
                 "{%0,%1,%2,%3}, {%4,%5,%6,%7}, {%8,%9}, {%0,%1,%2,%3};"        \
                 : "+f"((D)[0]), "+f"((D)[1]), "+f"((D)[2]), "+f"((D)[3])       \
                 : "r"((A)[0]), "r"((A)[1]), "r"((A)[2]), "r"((A)[3]),          \
                   "r"(B0), "r"(B1))
__device__ __forceinline__ uint32_t h2pack(float a, float b) {
    __half2 h = __floats2half2_rn(a, b);
    return *(uint32_t*)&h;
}

// ---------------------------------------------------------------------------
// Kernel 0: prep — u1 = W@a1, u2 = W@a2 (fp32), and cast W -> fp16.
// (verbatim from passing R13)
// ---------------------------------------------------------------------------
__global__ __launch_bounds__(256) void prep_kernel(const float* __restrict__ W,
                                                   const float* __restrict__ A) {
    __shared__ float a1s[FEAT], a2s[FEAT];
    const int t = threadIdx.x;
    a1s[t] = A[t];
    a2s[t] = A[FEAT + t];
    __syncthreads();
    const int lane = t & 31, wid = t >> 5;
    const int r = blockIdx.x * 8 + wid;
    const float* wr = W + (size_t)r * FEAT;
    float s1 = 0.f, s2 = 0.f;
#pragma unroll
    for (int q = 0; q < 2; q++) {
        int f = lane * 8 + q * 4;
        float4 w4 = *(const float4*)(wr + f);
        uint2 hp;
        hp.x = h2pack(w4.x, w4.y);
        hp.y = h2pack(w4.z, w4.w);
        *(uint2*)(d_Wh + (size_t)r * FEAT + f) = hp;
        s1 += w4.x * a1s[f] + w4.y * a1s[f + 1] + w4.z * a1s[f + 2] + w4.w * a1s[f + 3];
        s2 += w4.x * a2s[f] + w4.y * a2s[f + 1] + w4.z * a2s[f + 2] + w4.w * a2s[f + 3];
    }
#pragma unroll
    for (int o = 16; o > 0; o >>= 1) {
        s1 += __shfl_xor_sync(0xffffffffu, s1, o);
        s2 += __shfl_xor_sync(0xffffffffu, s2, o);
    }
    if (lane == 0) {
        d_U[0][r] = s1;
        d_U[1][r] = s2;
    }
}

// ---------------------------------------------------------------------------
// Kernel 1: spack — s1 = X.u1, s2 = X.u2 (fp32 exact) + separable exp factors.
// (verbatim from passing R13)
// ---------------------------------------------------------------------------
__global__ __launch_bounds__(256) void spack_kernel(const float* __restrict__ X) {
    const int lane = threadIdx.x & 31;
    const int wid  = threadIdx.x >> 5;
    const int row  = blockIdx.x * 8 + wid;
    const float* xr = X + (size_t)row * FEAT;
    float s1 = 0.f, s2 = 0.f;
#pragma unroll
    for (int q = 0; q < 2; q++) {
        int f = lane * 8 + q * 4;
        float4 xv = *(const float4*)(xr + f);
        float4 u1 = *(const float4*)(&d_U[0][f]);
        float4 u2 = *(const float4*)(&d_U[1][f]);
        s1 += xv.x * u1.x + xv.y * u1.y + xv.z * u1.z + xv.w * u1.w;
        s2 += xv.x * u2.x + xv.y * u2.y + xv.z * u2.z + xv.w * u2.w;
    }
#pragma unroll
    for (int o = 16; o > 0; o >>= 1) {
        s1 += __shfl_xor_sync(0xffffffffu, s1, o);
        s2 += __shfl_xor_sync(0xffffffffu, s2, o);
    }
    if (lane == 0) {
        d_G1[row] = make_float4(s1, expf(s1), expf(0.2f * s1), 0.f);
        d_G2[row] = make_float4(s2, expf(s2), expf(0.2f * s2), 0.f);
    }
}

// ---------------------------------------------------------------------------
// Kernel 2: d_Hh = fp16(X @ W) via HMMA (verbatim from passing R13).
// ---------------------------------------------------------------------------
#define GH_SMEM (FEAT * 512)   // 131072

__global__ __launch_bounds__(256, 1) void gemm_h_mma(const float* __restrict__ X) {
    extern __shared__ char sm2[];
    const uint32_t smb = smem_u32(sm2);
    const int t    = threadIdx.x;
    const int wid  = t >> 5, lane = t & 31;
    const int i0   = blockIdx.x * 64;
    const int wM   = wid & 1;
    const int wF   = wid >> 1;

#pragma unroll
    for (int m = 0; m < 32; m++) {
        int e = t + 256 * m;
        int k = e >> 5, c = e & 31;
        cp16(sm2 + k * 512 + ((c ^ (k & 7)) << 4), d_Wh + (size_t)k * FEAT + c * 8);
    }
    cp_commit();
    cp_wait<0>();
    __syncthreads();

    float acc[2][8][4];
#pragma unroll
    for (int a = 0; a < 2; a++)
#pragma unroll
        for (int b = 0; b < 8; b++)
#pragma unroll
            for (int c = 0; c < 4; c++) acc[a][b][c] = 0.f;

    const int g  = lane >> 2;
    const int tg = lane & 3;
    const int bj_lane = lane & 15;
    const int bf_off  = (lane >> 4) * 8;

#pragma unroll 2
    for (int ks = 0; ks < 16; ks++) {
        const int k0 = ks * 16;
        uint32_t afr[2][4];
#pragma unroll
        for (int mf = 0; mf < 2; mf++) {
            const float* xb = X + (size_t)(i0 + wM * 32 + mf * 16 + g) * FEAT + k0 + tg * 2;
            float2 v00 = *(const float2*)(xb);
            float2 v10 = *(const float2*)(xb + 8 * FEAT);
            float2 v01 = *(const float2*)(xb + 8);
            float2 v11 = *(const float2*)(xb + 8 * FEAT + 8);
            afr[mf][0] = h2pack(v00.x, v00.y);
            afr[mf][1] = h2pack(v10.x, v10.y);
            afr[mf][2] = h2pack(v01.x, v01.y);
            afr[mf][3] = h2pack(v11.x, v11.y);
        }
        const int j = k0 + bj_lane;
        const uint32_t brow = smb + j * 512;
        const uint32_t jx   = (uint32_t)(j & 7) << 4;
        uint32_t bfr[4][4];
#pragma unroll
        for (int nf = 0; nf < 4; nf++) {
            int f = wF * 64 + nf * 16 + bf_off;
            uint32_t boff = ((uint32_t)(f >> 3) << 4) ^ jx;
            LDSM4T(bfr[nf], brow + boff);
        }
#pragma unroll
        for (int mf = 0; mf < 2; mf++)
#pragma unroll
            for (int n8 = 0; n8 < 8; n8++)
                MMA16816(acc[mf][n8], afr[mf],
                         bfr[n8 >> 1][(n8 & 1) * 2],
                         bfr[n8 >> 1][(n8 & 1) * 2 + 1]);
    }

#pragma unroll
    for (int mf = 0; mf < 2; mf++) {
        const int ra = i0 + wM * 32 + mf * 16 + g;
#pragma unroll
        for (int n8 = 0; n8 < 8; n8++) {
            const int col = wF * 64 + n8 * 8 + tg * 2;
            *(uint32_t*)(d_Hh + (size_t)ra * FEAT + col) =
                h2pack(acc[mf][n8][0], acc[mf][n8][1]);
            *(uint32_t*)(d_Hh + (size_t)(ra + 8) * FEAT + col) =
                h2pack(acc[mf][n8][2], acc[mf][n8][3]);
        }
    }
}

// ---------------------------------------------------------------------------
// Kernel 3: flash-style fused masked-softmax @ h, fp16 HMMA. BM=64, BK=32,
// 1 CTA/SM (R13 shape — proven lowest-traffic config), with:
//  * TRIPLE-buffered H and P -> ONE __syncthreads() per tile
//    (single barrier both publishes cp.async data across threads — race fix —
//     and P[s]; 3 live buffers make the one-barrier schedule hazard-free)
//  * all 12 LDSM issues per tile hoisted ahead of the 32 MMAs
// SMEM layout (dynamic):
//   Hs   : 3 x 16384  (H tile 32(j) x 256(f) fp16, 16B-chunk XOR swizzle) @ 0
//   adjs : 4 x 8192   (adj tile 64 x 32 i32, linear)                     @ 49152
//   Ps   : 3 x 5120   (P tile 64 x 32 fp16, row pitch 80B)               @ 81920
//   g2s  : 4 x 512    (32 float4)                                        @ 97280
//   zsh  : 64 floats                                                     @ 99328
#define HS_OFF   0
#define HS_SZ    16384
#define ADJ_OFF  49152
#define ADJ_SZ   8192
#define PS_OFF   81920
#define PS_SZ    5120
#define G2_OFF   97280
#define ZSH_OFF  99328
#define SMEMM_BYTES 99584
#define PPITCH_B 80     // P row pitch in bytes (40 halves)

__global__ __launch_bounds__(THREADS, 1) void gat_mma_kernel(const int* __restrict__ ADJ,
                                                             float* __restrict__ OUT) {
    extern __shared__ char sm[];
    const uint32_t smb = smem_u32(sm);
    const int t    = threadIdx.x;
    const int wid  = t >> 5, lane = t & 31;
    const int i0   = blockIdx.x * BM;
    const int g    = t & 7;       // P-gen: k-quad (cols 4g..4g+3)
    const int r0   = t >> 3;      // P-gen: row base (rows r0, r0+32)
    const int wM   = wid & 1;     // warp M tile: rows wM*32 .. +31
    const int wF   = wid >> 1;    // warp F tile: cols wF*64 .. +63

    float4 g1v[2];
#pragma unroll
    for (int m = 0; m < 2; m++) g1v[m] = d_G1[i0 + r0 + 32 * m];
    float zac[2] = {0.f, 0.f};

    float acc[2][8][4];           // [mfrag][n8frag][reg]
#pragma unroll
    for (int a = 0; a < 2; a++)
#pragma unroll
        for (int b = 0; b < 8; b++)
#pragma unroll
            for (int c = 0; c < 4; c++) acc[a][b][c] = 0.f;

    // ---- async loaders ----
    auto load_adj = [&](int s, int ab) {
        const int j0 = s * BK;
        char* adst = sm + ADJ_OFF + ab * ADJ_SZ;
#pragma unroll
        for (int m = 0; m < 2; m++) {
            int e = t + 256 * m;
            int r = e >> 3, c = e & 7;
            cp16(adst + r * 128 + c * 16, ADJ + (size_t)(i0 + r) * N_NODES + j0 + c * 4);
        }
        if (t < 32) cp16(sm + G2_OFF + ab * 512 + t * 16, d_G2 + j0 + t);
    };
    auto load_h = [&](int s, int hb) {
        const int j0 = s * BK;
        char* hdst = sm + HS_OFF + hb * HS_SZ;
#pragma unroll
        for (int m = 0; m < 4; m++) {
            int e = t + 256 * m;
            int j = e >> 5, c = e & 31;
            cp16(hdst + j * 512 + ((c ^ (j & 7)) << 4),
                 d_Hh + (size_t)(j0 + j) * FEAT + c * 8);
        }
    };

    // ---- P-tile generation for tile sn: w = adj ? exp(lrelu(s1+s2)) : 0 ----
    auto do_genp = [&](int sn) {
        const int ab = sn & 3, pb = sn % 3;
        const float4* g2b = (const float4*)(sm + G2_OFF + ab * 512) + g * 4;
        float4 G[4];
#pragma unroll
        for (int j = 0; j < 4; j++) G[j] = g2b[j];
        const int4* abase = (const int4*)(sm + ADJ_OFF + ab * ADJ_SZ);
        char* pbase = sm + PS_OFF + pb * PS_SZ;
#pragma unroll
        for (int m = 0; m < 2; m++) {
            const int r = r0 + 32 * m;
            int4 av = abase[r * 8 + g];
            int msk[4] = {av.x, av.y, av.z, av.w};
            __half hw[4];
#pragma unroll
            for (int j = 0; j < 4; j++) {
                float x = g1v[m].x + G[j].x;
                float e = (x >= 0.f ? g1v[m].y : g1v[m].z) *
                          (x >= 0.f ? G[j].y : G[j].z);
                e = (msk[j] != 0) ? e : 0.f;
                hw[j] = __float2half_rn(e);
                zac[m] += __half2float(hw[j]);   // Z from the SAME rounded w
            }
            __half2 p01 = __halves2half2(hw[0], hw[1]);
            __half2 p23 = __halves2half2(hw[2], hw[3]);
            uint2 pk;
            pk.x = *(uint32_t*)&p01;
            pk.y = *(uint32_t*)&p23;
            *(uint2*)(pbase + r * PPITCH_B + g * 8) = pk;
        }
    };

    // precomputed ldmatrix address pieces
    const uint32_t a_base = smb + PS_OFF +
                            (uint32_t)(wM * 32 + (lane & 15)) * PPITCH_B +
                            (uint32_t)((lane >> 4) * 8) * 2;
    const int bj_lane = lane & 15;           // row within k-half
    const int bf_off  = (lane >> 4) * 8;     // col offset within n16

    // ---- HMMA tile s: all LDSM hoisted, then 32 MMAs (warp tile 32x64) ----
    auto do_mma = [&](int s) {
        const int cur = s % 3;
        const uint32_t hbase = smb + HS_OFF + cur * HS_SZ;
        const uint32_t acur  = a_base + (uint32_t)cur * PS_SZ;
        uint32_t afr[2][2][4];    // [kh][mf]
        uint32_t bfr[2][4][4];    // [kh][nf]
#pragma unroll
        for (int kh = 0; kh < 2; kh++) {
            LDSM4(afr[kh][0], acur + kh * 32);                 // rows wM*32..+15
            LDSM4(afr[kh][1], acur + kh * 32 + 16 * PPITCH_B); // rows +16..+31
            const int j   = kh * 16 + bj_lane;
            const uint32_t brow = hbase + j * 512;
            const uint32_t jx   = (uint32_t)(j & 7) << 4;
#pragma unroll
            for (int nf = 0; nf < 4; nf++) {
                int f = wF * 64 + nf * 16 + bf_off;
                uint32_t boff = ((uint32_t)(f >> 3) << 4) ^ jx;
                LDSM4T(bfr[kh][nf], brow + boff);
            }
        }
#pragma unroll
        for (int kh = 0; kh < 2; kh++)
#pragma unroll
            for (int mf = 0; mf < 2; mf++)
#pragma unroll
                for (int n8 = 0; n8 < 8; n8++)
                    MMA16816(acc[mf][n8], afr[kh][mf],
                             bfr[kh][n8 >> 1][(n8 & 1) * 2],
                             bfr[kh][n8 >> 1][(n8 & 1) * 2 + 1]);
    };

    // ---- prologue: adj[0] | adj[1]+H[0] in flight; gen P[0] ----
    load_adj(0, 0);
    cp_commit();
    load_adj(1, 1);
    load_h(0, 0);
    cp_commit();
    cp_wait<1>();          // adj[0], g2[0] resident (own groups)
    __syncthreads();       // publish across threads (race fix)
    do_genp(0);            // P[0]; published by the loop's first barrier

    // ---- main loop: ONE sync per tile; genP(s+1) overlapped with MMA(s) ----
    for (int s = 0; s < NTILES; ++s) {
        if (s + 1 < NTILES) {
            load_h(s + 1, (s + 1) % 3);
            if (s + 2 < NTILES) load_adj(s + 2, (s + 2) & 3);
            cp_commit();
            cp_wait<1>();  // group {H[s], adj[s+1], g2[s+1]} complete (own)
        } else {
            cp_wait<0>();
        }
        __syncthreads();   // publishes cp data AND P[s] across all threads
        // phase-staggered: each SMSP gets one ALU-first and one MMA-first warp
        if ((wid & 4) == 0) {
            if (s + 1 < NTILES) do_genp(s + 1);
            do_mma(s);
        } else {
            do_mma(s);
            if (s + 1 < NTILES) do_genp(s + 1);
        }
    }

    // ---- Z reduction: threads sharing a row differ only in g (low 3 bits) ----
#pragma unroll
    for (int o = 1; o < 8; o <<= 1)
#pragma unroll
        for (int m = 0; m < 2; m++) zac[m] += __shfl_xor_sync(0xffffffffu, zac[m], o);
    float* zsh = (float*)(sm + ZSH_OFF);
    if (g == 0)
#pragma unroll
        for (int m = 0; m < 2; m++) zsh[r0 + 32 * m] = zac[m];
    __syncthreads();

    // ---- epilogue: divide by Z, elu, store ----
#pragma unroll
    for (int mf = 0; mf < 2; mf++) {
        const int ra = wM * 32 + mf * 16 + (lane >> 2);  // local row a
        const float rza = 1.0f / zsh[ra];
        const float rzb = 1.0f / zsh[ra + 8];
        float* orow_a = OUT + (size_t)(i0 + ra) * FEAT;
        float* orow_b = OUT + (size_t)(i0 + ra + 8) * FEAT;
#pragma unroll
        for (int n8 = 0; n8 < 8; n8++) {
            const int col = wF * 64 + n8 * 8 + (lane & 3) * 2;
            float v0 = acc[mf][n8][0] * rza, v1 = acc[mf][n8][1] * rza;
            float v2 = acc[mf][n8][2] * rzb, v3 = acc[mf][n8][3] * rzb;
            v0 = (v0 > 0.f) ? v0 : expm1f(v0);
            v1 = (v1 > 0.f) ? v1 : expm1f(v1);
            v2 = (v2 > 0.f) ? v2 : expm1f(v2);
            v3 = (v3 > 0.f) ? v3 : expm1f(v3);
            *(float2*)(orow_a + col) = make_float2(v0, v1);
            *(float2*)(orow_b + col) = make_float2(v2, v3);
        }
    }
}

// ---------------------------------------------------------------------------
extern "C" void kernel_launch(void* const* d_in, const int* in_sizes, int n_in,
                              void* d_out, int out_size) {
    (void)in_sizes; (void)n_in; (void)out_size;
    const float* X   = (const float*)d_in[0];   // input [8192,256] f32
    const int*   ADJ = (const int*)d_in[1];     // adj   [8192,8192] i32
    const float* W   = (const float*)d_in[2];   // W     [256,256] f32
    const float* A   = (const float*)d_in[3];   // a     [512,1]  f32
    float* OUT = (float*)d_out;                 // [8192,256] f32

    prep_kernel<<<FEAT / 8, 256>>>(W, A);
    spack_kernel<<<N_NODES / 8, 256>>>(X);
    cudaFuncSetAttribute(gemm_h_mma,
                         cudaFuncAttributeMaxDynamicSharedMemorySize, GH_SMEM);
    gemm_h_mma<<<N_NODES / 64, 256, GH_SMEM>>>(X);
    cudaFuncSetAttribute(gat_mma_kernel,
                         cudaFuncAttributeMaxDynamicSharedMemorySize, SMEMM_BYTES);
    gat_mma_kernel<<<N_NODES / BM, THREADS, SMEMM_BYTES>>>(ADJ, OUT);
}

// round 17
// speedup vs baseline: 1.3935x; 1.0437x over previous
#include <cuda_runtime.h>
#include <cuda_fp16.h>
#include <cstdint>
#include <cstddef>

#define N_NODES 8192
#define FEAT    256
#define BM      64           // output rows per CTA (main kernel)
#define BK      32           // k-tile (nodes)
#define NTILES  (N_NODES / BK)   // 256
#define THREADS 512          // 8 MMA warps + 8 producer warps

// Scratch (no runtime allocation allowed)
__device__ __half d_Hh[N_NODES * FEAT];  // h in fp16 (MMA B operand), row-major
__device__ __half d_Wh[FEAT * FEAT];     // W in fp16
__device__ float  d_U[2][FEAT];          // u1 = W@a1, u2 = W@a2
__device__ float4 d_G1[N_NODES];         // (s1, exp(s1), exp(0.2 s1), 0)
__device__ float4 d_G2[N_NODES];         // (s2, exp(s2), exp(0.2 s2), 0)

// ---------------------------------------------------------------------------
// helpers
// ---------------------------------------------------------------------------
__device__ __forceinline__ uint32_t smem_u32(const void* p) {
    uint32_t a;
    asm("{ .reg .u64 t; cvta.to.shared.u64 t, %1; cvt.u32.u64 %0, t; }" : "=r"(a) : "l"(p));
    return a;
}
__device__ __forceinline__ void cp16(void* dst, const void* src) {
    unsigned d = (unsigned)__cvta_generic_to_shared(dst);
    asm volatile("cp.async.cg.shared.global [%0], [%1], 16;" :: "r"(d), "l"(src));
}
__device__ __forceinline__ void cp_commit() {
    asm volatile("cp.async.commit_group;" ::: "memory");
}
template <int N>
__device__ __forceinline__ void cp_wait() {
    asm volatile("cp.async.wait_group %0;" :: "n"(N) : "memory");
}
#define LDSM4(R, addr)                                                          \
    asm volatile("ldmatrix.sync.aligned.m8n8.x4.shared.b16 {%0,%1,%2,%3}, [%4];" \
                 : "=r"((R)[0]), "=r"((R)[1]), "=r"((R)[2]), "=r"((R)[3])       \
                 : "r"(addr))
#define LDSM4T(R, addr)                                                               \
    asm volatile("ldmatrix.sync.aligned.m8n8.x4.trans.shared.b16 {%0,%1,%2,%3}, [%4];" \
                 : "=r"((R)[0]), "=r"((R)[1]), "=r"((R)[2]), "=r"((R)[3])             \
                 : "r"(addr))
#define MMA16816(D, A, B0, B1)                                                  \
    asm volatile("mma.sync.aligned.m16n8k16.row.col.f32.f16.f16.f32 "           \
                 "{%0,%1,%2,%3}, {%4,%5,%6,%7}, {%8,%9}, {%0,%1,%2,%3};"        \
                 : "+f"((D)[0]), "+f"((D)[1]), "+f"((D)[2]), "+f"((D)[3])       \
                 : "r"((A)[0]), "r"((A)[1]), "r"((A)[2]), "r"((A)[3]),          \
                   "r"(B0), "r"(B1))
__device__ __forceinline__ uint32_t h2pack(float a, float b) {
    __half2 h = __floats2half2_rn(a, b);
    return *(uint32_t*)&h;
}

// ---------------------------------------------------------------------------
// Kernel 0: prep — u1 = W@a1, u2 = W@a2 (fp32), and cast W -> fp16.
// (verbatim from passing R13)
// ---------------------------------------------------------------------------
__global__ __launch_bounds__(256) void prep_kernel(const float* __restrict__ W,
                                                   const float* __restrict__ A) {
    __shared__ float a1s[FEAT], a2s[FEAT];
    const int t = threadIdx.x;
    a1s[t] = A[t];
    a2s[t] = A[FEAT + t];
    __syncthreads();
    const int lane = t & 31, wid = t >> 5;
    const int r = blockIdx.x * 8 + wid;
    const float* wr = W + (size_t)r * FEAT;
    float s1 = 0.f, s2 = 0.f;
#pragma unroll
    for (int q = 0; q < 2; q++) {
        int f = lane * 8 + q * 4;
        float4 w4 = *(const float4*)(wr + f);
        uint2 hp;
        hp.x = h2pack(w4.x, w4.y);
        hp.y = h2pack(w4.z, w4.w);
        *(uint2*)(d_Wh + (size_t)r * FEAT + f) = hp;
        s1 += w4.x * a1s[f] + w4.y * a1s[f + 1] + w4.z * a1s[f + 2] + w4.w * a1s[f + 3];
        s2 += w4.x * a2s[f] + w4.y * a2s[f + 1] + w4.z * a2s[f + 2] + w4.w * a2s[f + 3];
    }
#pragma unroll
    for (int o = 16; o > 0; o >>= 1) {
        s1 += __shfl_xor_sync(0xffffffffu, s1, o);
        s2 += __shfl_xor_sync(0xffffffffu, s2, o);
    }
    if (lane == 0) {
        d_U[0][r] = s1;
        d_U[1][r] = s2;
    }
}

// ---------------------------------------------------------------------------
// Kernel 1: spack — s1 = X.u1, s2 = X.u2 (fp32 exact) + separable exp factors.
// (verbatim from passing R13)
// ---------------------------------------------------------------------------
__global__ __launch_bounds__(256) void spack_kernel(const float* __restrict__ X) {
    const int lane = threadIdx.x & 31;
    const int wid  = threadIdx.x >> 5;
    const int row  = blockIdx.x * 8 + wid;
    const float* xr = X + (size_t)row * FEAT;
    float s1 = 0.f, s2 = 0.f;
#pragma unroll
    for (int q = 0; q < 2; q++) {
        int f = lane * 8 + q * 4;
        float4 xv = *(const float4*)(xr + f);
        float4 u1 = *(const float4*)(&d_U[0][f]);
        float4 u2 = *(const float4*)(&d_U[1][f]);
        s1 += xv.x * u1.x + xv.y * u1.y + xv.z * u1.z + xv.w * u1.w;
        s2 += xv.x * u2.x + xv.y * u2.y + xv.z * u2.z + xv.w * u2.w;
    }
#pragma unroll
    for (int o = 16; o > 0; o >>= 1) {
        s1 += __shfl_xor_sync(0xffffffffu, s1, o);
        s2 += __shfl_xor_sync(0xffffffffu, s2, o);
    }
    if (lane == 0) {
        d_G1[row] = make_float4(s1, expf(s1), expf(0.2f * s1), 0.f);
        d_G2[row] = make_float4(s2, expf(s2), expf(0.2f * s2), 0.f);
    }
}

// ---------------------------------------------------------------------------
// Kernel 2: d_Hh = fp16(X @ W) via HMMA (verbatim from passing R13).
// ---------------------------------------------------------------------------
#define GH_SMEM (FEAT * 512)   // 131072

__global__ __launch_bounds__(256, 1) void gemm_h_mma(const float* __restrict__ X) {
    extern __shared__ char sm2[];
    const uint32_t smb = smem_u32(sm2);
    const int t    = threadIdx.x;
    const int wid  = t >> 5, lane = t & 31;
    const int i0   = blockIdx.x * 64;
    const int wM   = wid & 1;
    const int wF   = wid >> 1;

#pragma unroll
    for (int m = 0; m < 32; m++) {
        int e = t + 256 * m;
        int k = e >> 5, c = e & 31;
        cp16(sm2 + k * 512 + ((c ^ (k & 7)) << 4), d_Wh + (size_t)k * FEAT + c * 8);
    }
    cp_commit();
    cp_wait<0>();
    __syncthreads();

    float acc[2][8][4];
#pragma unroll
    for (int a = 0; a < 2; a++)
#pragma unroll
        for (int b = 0; b < 8; b++)
#pragma unroll
            for (int c = 0; c < 4; c++) acc[a][b][c] = 0.f;

    const int g  = lane >> 2;
    const int tg = lane & 3;
    const int bj_lane = lane & 15;
    const int bf_off  = (lane >> 4) * 8;

#pragma unroll 2
    for (int ks = 0; ks < 16; ks++) {
        const int k0 = ks * 16;
        uint32_t afr[2][4];
#pragma unroll
        for (int mf = 0; mf < 2; mf++) {
            const float* xb = X + (size_t)(i0 + wM * 32 + mf * 16 + g) * FEAT + k0 + tg * 2;
            float2 v00 = *(const float2*)(xb);
            float2 v10 = *(const float2*)(xb + 8 * FEAT);
            float2 v01 = *(const float2*)(xb + 8);
            float2 v11 = *(const float2*)(xb + 8 * FEAT + 8);
            afr[mf][0] = h2pack(v00.x, v00.y);
            afr[mf][1] = h2pack(v10.x, v10.y);
            afr[mf][2] = h2pack(v01.x, v01.y);
            afr[mf][3] = h2pack(v11.x, v11.y);
        }
        const int j = k0 + bj_lane;
        const uint32_t brow = smb + j * 512;
        const uint32_t jx   = (uint32_t)(j & 7) << 4;
        uint32_t bfr[4][4];
#pragma unroll
        for (int nf = 0; nf < 4; nf++) {
            int f = wF * 64 + nf * 16 + bf_off;
            uint32_t boff = ((uint32_t)(f >> 3) << 4) ^ jx;
            LDSM4T(bfr[nf], brow + boff);
        }
#pragma unroll
        for (int mf = 0; mf < 2; mf++)
#pragma unroll
            for (int n8 = 0; n8 < 8; n8++)
                MMA16816(acc[mf][n8], afr[mf],
                         bfr[n8 >> 1][(n8 & 1) * 2],
                         bfr[n8 >> 1][(n8 & 1) * 2 + 1]);
    }

#pragma unroll
    for (int mf = 0; mf < 2; mf++) {
        const int ra = i0 + wM * 32 + mf * 16 + g;
#pragma unroll
        for (int n8 = 0; n8 < 8; n8++) {
            const int col = wF * 64 + n8 * 8 + tg * 2;
            *(uint32_t*)(d_Hh + (size_t)ra * FEAT + col) =
                h2pack(acc[mf][n8][0], acc[mf][n8][1]);
            *(uint32_t*)(d_Hh + (size_t)(ra + 8) * FEAT + col) =
                h2pack(acc[mf][n8][2], acc[mf][n8][3]);
        }
    }
}

// ---------------------------------------------------------------------------
// Kernel 3: flash-style fused masked-softmax @ h, fp16 HMMA.
// WARP-SPECIALIZED, 512 threads: warps 0-7 = pure MMA (32x64 tiles, 12 LDSM +
// 32 HMMA per tile, nothing else); warps 8-15 = producers (all cp.async, all
// genP, Z). Same BM=64/BK=32 per-SM smem traffic as the proven R13 kernel.
// One __syncthreads per tile; producers follow cp_wait -> barrier -> consume.
// SMEM layout (dynamic):
//   Hs   : 3 x 16384  (H tile 32(j) x 256(f) fp16, 16B-chunk XOR swizzle) @ 0
//   adjs : 4 x 8192   (adj tile 64 x 32 i32, linear)                     @ 49152
//   Ps   : 3 x 5120   (P tile 64 x 32 fp16, row pitch 80B)               @ 81920
//   g2s  : 4 x 512    (32 float4)                                        @ 97280
//   zsh  : 64 floats                                                     @ 99328
#define HS_OFF   0
#define HS_SZ    16384
#define ADJ_OFF  49152
#define ADJ_SZ   8192
#define PS_OFF   81920
#define PS_SZ    5120
#define G2_OFF   97280
#define ZSH_OFF  99328
#define SMEMM_BYTES 99584
#define PPITCH_B 80     // P row pitch in bytes (40 halves)

__global__ __launch_bounds__(THREADS, 1) void gat_mma_kernel(const int* __restrict__ ADJ,
                                                             float* __restrict__ OUT) {
    extern __shared__ char sm[];
    const uint32_t smb = smem_u32(sm);
    const int t    = threadIdx.x;
    const int wid  = t >> 5, lane = t & 31;
    const int i0   = blockIdx.x * BM;
    const bool producer = (wid >= 8);
    const int tp   = t & 255;     // producer-local thread id (0..255)
    const int g    = tp & 7;      // P-gen: k-quad (cols 4g..4g+3)
    const int r0   = tp >> 3;     // P-gen: row base (rows r0, r0+32)
    const int wM   = wid & 1;     // MMA warp M tile: rows wM*32 .. +31
    const int wF   = (wid >> 1) & 3; // MMA warp F tile: cols wF*64 .. +63

    float4 g1v[2];
#pragma unroll
    for (int m = 0; m < 2; m++) g1v[m] = d_G1[i0 + r0 + 32 * m];
    float zac[2] = {0.f, 0.f};

    float acc[2][8][4];           // [mfrag][n8frag][reg] (MMA warps only)
#pragma unroll
    for (int a = 0; a < 2; a++)
#pragma unroll
        for (int b = 0; b < 8; b++)
#pragma unroll
            for (int c = 0; c < 4; c++) acc[a][b][c] = 0.f;

    // ---- async loaders (producer threads: tp in 0..255) ----
    auto load_adj = [&](int s, int ab) {
        const int j0 = s * BK;
        char* adst = sm + ADJ_OFF + ab * ADJ_SZ;
#pragma unroll
        for (int m = 0; m < 2; m++) {
            int e = tp + 256 * m;
            int r = e >> 3, c = e & 7;
            cp16(adst + r * 128 + c * 16, ADJ + (size_t)(i0 + r) * N_NODES + j0 + c * 4);
        }
        if (tp < 32) cp16(sm + G2_OFF + ab * 512 + tp * 16, d_G2 + j0 + tp);
    };
    auto load_h = [&](int s, int hb) {
        const int j0 = s * BK;
        char* hdst = sm + HS_OFF + hb * HS_SZ;
#pragma unroll
        for (int m = 0; m < 4; m++) {
            int e = tp + 256 * m;
            int j = e >> 5, c = e & 31;
            cp16(hdst + j * 512 + ((c ^ (j & 7)) << 4),
                 d_Hh + (size_t)(j0 + j) * FEAT + c * 8);
        }
    };

    // ---- P-tile generation for tile sn (producers) ----
    auto do_genp = [&](int sn) {
        const int ab = sn & 3, pb = sn % 3;
        const float4* g2b = (const float4*)(sm + G2_OFF + ab * 512) + g * 4;
        float4 G[4];
#pragma unroll
        for (int j = 0; j < 4; j++) G[j] = g2b[j];
        const int4* abase = (const int4*)(sm + ADJ_OFF + ab * ADJ_SZ);
        char* pbase = sm + PS_OFF + pb * PS_SZ;
#pragma unroll
        for (int m = 0; m < 2; m++) {
            const int r = r0 + 32 * m;
            int4 av = abase[r * 8 + g];
            int msk[4] = {av.x, av.y, av.z, av.w};
            __half hw[4];
#pragma unroll
            for (int j = 0; j < 4; j++) {
                float x = g1v[m].x + G[j].x;
                float e = (x >= 0.f ? g1v[m].y : g1v[m].z) *
                          (x >= 0.f ? G[j].y : G[j].z);
                e = (msk[j] != 0) ? e : 0.f;
                hw[j] = __float2half_rn(e);
                zac[m] += __half2float(hw[j]);   // Z from the SAME rounded w
            }
            __half2 p01 = __halves2half2(hw[0], hw[1]);
            __half2 p23 = __halves2half2(hw[2], hw[3]);
            uint2 pk;
            pk.x = *(uint32_t*)&p01;
            pk.y = *(uint32_t*)&p23;
            *(uint2*)(pbase + r * PPITCH_B + g * 8) = pk;
        }
    };

    // precomputed ldmatrix address pieces (MMA warps)
    const uint32_t a_base = smb + PS_OFF +
                            (uint32_t)(wM * 32 + (lane & 15)) * PPITCH_B +
                            (uint32_t)((lane >> 4) * 8) * 2;
    const int bj_lane = lane & 15;           // row within k-half
    const int bf_off  = (lane >> 4) * 8;     // col offset within n16

    // ---- HMMA for tile s: acc += P[64x32] @ H[32x256] (warp tile 32x64) ----
    auto do_mma = [&](int s) {
        const int cur = s % 3;
        const uint32_t hbase = smb + HS_OFF + cur * HS_SZ;
        const uint32_t acur  = a_base + (uint32_t)cur * PS_SZ;
#pragma unroll
        for (int kh = 0; kh < 2; kh++) {
            uint32_t afr[2][4];
            LDSM4(afr[0], acur + kh * 32);                 // rows wM*32..+15
            LDSM4(afr[1], acur + kh * 32 + 16 * PPITCH_B); // rows +16..+31
            const int j   = kh * 16 + bj_lane;
            const uint32_t brow = hbase + j * 512;
            const uint32_t jx   = (uint32_t)(j & 7) << 4;
            uint32_t bfr[4][4];
#pragma unroll
            for (int nf = 0; nf < 4; nf++) {
                int f = wF * 64 + nf * 16 + bf_off;
                uint32_t boff = ((uint32_t)(f >> 3) << 4) ^ jx;
                LDSM4T(bfr[nf], brow + boff);
            }
#pragma unroll
            for (int mf = 0; mf < 2; mf++)
#pragma unroll
                for (int n8 = 0; n8 < 8; n8++)
                    MMA16816(acc[mf][n8], afr[mf],
                             bfr[n8 >> 1][(n8 & 1) * 2],
                             bfr[n8 >> 1][(n8 & 1) * 2 + 1]);
        }
    };

    // ---- prologue (producers fill the pipe 2 tiles deep) ----
    if (producer) {
        load_adj(0, 0);                 // G_a = {adj0, g2_0}
        cp_commit();
        load_adj(1, 1);                 // G_b = {adj1, g2_1, H0}
        load_h(0, 0);
        cp_commit();
        load_adj(2, 2);                 // G_c = {adj2, g2_2, H1}
        load_h(1, 1);
        cp_commit();
        cp_wait<2>();                   // G_a done
    }
    __syncthreads();                    // adj0/g2_0 visible
    if (producer) {
        do_genp(0);                     // P[0]
        cp_wait<1>();                   // G_b done (adj1, H0)
    }
    __syncthreads();                    // H0, P0, adj1 visible — enter loop

    // ---- main loop: ONE sync per tile; producers feed, MMA warps consume ----
    for (int s = 0; s < NTILES; ++s) {
        if (producer) {
            if (s + 1 < NTILES) do_genp(s + 1);          // adj[s+1] visible
            if (s + 2 < NTILES) load_h(s + 2, (s + 2) % 3);
            if (s + 3 < NTILES) load_adj(s + 3, (s + 3) & 3);
            cp_commit();                                  // G_s
            cp_wait<1>();   // G_{s-1} = {H[s+1], adj[s+2]} complete (own)
        } else {
            do_mma(s);      // H[s], P[s] visible from top barrier
        }
        __syncthreads();    // publish cp data + P[s+1] across all threads
    }

    // ---- Z reduction (producers): threads sharing a row differ only in g ----
    if (producer) {
#pragma unroll
        for (int o = 1; o < 8; o <<= 1)
#pragma unroll
            for (int m = 0; m < 2; m++) zac[m] += __shfl_xor_sync(0xffffffffu, zac[m], o);
        float* zsh = (float*)(sm + ZSH_OFF);
        if (g == 0)
#pragma unroll
            for (int m = 0; m < 2; m++) zsh[r0 + 32 * m] = zac[m];
    }
    __syncthreads();

    // ---- epilogue (MMA warps): divide by Z, elu, store ----
    if (!producer) {
        const float* zsh = (const float*)(sm + ZSH_OFF);
#pragma unroll
        for (int mf = 0; mf < 2; mf++) {
            const int ra = wM * 32 + mf * 16 + (lane >> 2);  // local row a
            const float rza = 1.0f / zsh[ra];
            const float rzb = 1.0f / zsh[ra + 8];
            float* orow_a = OUT + (size_t)(i0 + ra) * FEAT;
            float* orow_b = OUT + (size_t)(i0 + ra + 8) * FEAT;
#pragma unroll
            for (int n8 = 0; n8 < 8; n8++) {
                const int col = wF * 64 + n8 * 8 + (lane & 3) * 2;
                float v0 = acc[mf][n8][0] * rza, v1 = acc[mf][n8][1] * rza;
                float v2 = acc[mf][n8][2] * rzb, v3 = acc[mf][n8][3] * rzb;
                v0 = (v0 > 0.f) ? v0 : expm1f(v0);
                v1 = (v1 > 0.f) ? v1 : expm1f(v1);
                v2 = (v2 > 0.f) ? v2 : expm1f(v2);
                v3 = (v3 > 0.f) ? v3 : expm1f(v3);
                *(float2*)(orow_a + col) = make_float2(v0, v1);
                *(float2*)(orow_b + col) = make_float2(v2, v3);
            }
        }
    }
}

// ---------------------------------------------------------------------------
extern "C" void kernel_launch(void* const* d_in, const int* in_sizes, int n_in,
                              void* d_out, int out_size) {
    (void)in_sizes; (void)n_in; (void)out_size;
    const float* X   = (const float*)d_in[0];   // input [8192,256] f32
    const int*   ADJ = (const int*)d_in[1];     // adj   [8192,8192] i32
    const float* W   = (const float*)d_in[2];   // W     [256,256] f32
    const float* A   = (const float*)d_in[3];   // a     [512,1]  f32
    float* OUT = (float*)d_out;                 // [8192,256] f32

    prep_kernel<<<FEAT / 8, 256>>>(W, A);
    spack_kernel<<<N_NODES / 8, 256>>>(X);
    cudaFuncSetAttribute(gemm_h_mma,
                         cudaFuncAttributeMaxDynamicSharedMemorySize, GH_SMEM);
    gemm_h_mma<<<N_NODES / 64, 256, GH_SMEM>>>(X);
    cudaFuncSetAttribute(gat_mma_kernel,
                         cudaFuncAttributeMaxDynamicSharedMemorySize, SMEMM_BYTES);
    gat_mma_kernel<<<N_NODES / BM, THREADS, SMEMM_BYTES>>>(ADJ, OUT);
}